// round 13
// baseline (speedup 1.0000x reference)
#include <cuda_runtime.h>
#include <cstdint>
#include <math.h>

// ============================================================================
// Problem constants
// ============================================================================
#define MAXN    1048576
#define NSTEPS  8
#define NSEG    8               // 8 permutations (one per training step)
#define HALFB   512             // blocks per role in step kernel
#define GNT     128             // threads per block in step kernel

// --- permutation sort configuration ---
#define BBITS   11              // MSD bucket bits
#define NBKT    (1 << BBITS)    // 2048 buckets per segment
#define LOWBITS (32 - BBITS)    // 21 low key bits
#define LOWMASK ((1u << LOWBITS) - 1u)
#define POSBITS 21              // position field (N <= 2^20)
#define POSMASK ((1u << POSBITS) - 1u)
#define CAPR    768             // fixed region capacity (avg 512, +11 sigma)
#define SORT_T  128
#define SORT_I  6               // 128*6 = 768 = CAPR
#define CAPF    (SORT_T * SORT_I)
#define SUBB    8               // in-bucket counting-sort bits (key bits [13,21))
#define NSUB    (1 << SUBB)     // 256 sub-buckets, avg 3 elements each
#define M34     ((1ull << 34) - 1ull)   // residue: (rem13 key << 21) | pos
#define SCAT_T  512
#define SCAT_I  16
#define CHUNK   (SCAT_T * SCAT_I)   // 8192 elements per scatter CTA
#define CPAD    8               // cursor padding (32B stride)

struct SubKeys { unsigned k0[NSEG]; unsigned k1[NSEG]; };

// ============================================================================
// Static device scratch (no dynamic allocation allowed)
// ============================================================================
__device__ __align__(256) unsigned g_pay[NSEG * NBKT * (size_t)CAPR]; // positions only (4B)
__device__ __align__(256) unsigned g_v1[NSEG * MAXN];    // round-1 result
__device__ __align__(256) unsigned g_perms[NSEG * MAXN]; // final permutations
__device__ unsigned g_cursor[2][NSEG * NBKT * CPAD];
__device__ unsigned g_base[2][NSEG * NBKT];

__device__ float  g_P[73];                    // [0..63]=w1, [64..67]=b1, [68..71]=w2, [72]=b2
__device__ float  g_m[73];
__device__ float  g_v[73];
__device__ float  g_partial[2][73][HALFB];
__device__ double g_S[2][HALFB];
__device__ double g_G[2][73];
__device__ double g_Stot[2];
__device__ float  g_losses[NSTEPS];

// ============================================================================
// Threefry2x32 — exact JAX implementation
// ============================================================================
__host__ __device__ __forceinline__ void tf2x32(unsigned k0, unsigned k1,
                                                unsigned c0, unsigned c1,
                                                unsigned &o0, unsigned &o1) {
    unsigned ks0 = k0, ks1 = k1, ks2 = k0 ^ k1 ^ 0x1BD11BDAu;
    unsigned x0 = c0 + ks0, x1 = c1 + ks1;
#define TFR(r) { x0 += x1; x1 = (x1 << (r)) | (x1 >> (32 - (r))); x1 ^= x0; }
    TFR(13) TFR(15) TFR(26) TFR(6)
    x0 += ks1; x1 += ks2 + 1u;
    TFR(17) TFR(29) TFR(16) TFR(24)
    x0 += ks2; x1 += ks0 + 2u;
    TFR(13) TFR(15) TFR(26) TFR(6)
    x0 += ks0; x1 += ks1 + 3u;
    TFR(17) TFR(29) TFR(16) TFR(24)
    x0 += ks1; x1 += ks2 + 4u;
    TFR(13) TFR(15) TFR(26) TFR(6)
    x0 += ks2; x1 += ks0 + 5u;
#undef TFR
    o0 = x0; o1 = x1;
}

__device__ __forceinline__ unsigned rnd_bits(const SubKeys& sk, int s, unsigned p) {
    unsigned a, b;
    tf2x32(sk.k0[s], sk.k1[s], 0u, p, a, b);
    return a ^ b;   // partitionable-threefry 32-bit random_bits
}

// ============================================================================
// f32x2 packed-FMA helpers (Blackwell FFMA2 — PTX-only pattern)
// ============================================================================
__device__ __forceinline__ unsigned long long f2pack(float lo, float hi) {
    unsigned long long r;
    asm("mov.b64 %0, {%1, %2};" : "=l"(r) : "f"(lo), "f"(hi));
    return r;
}
__device__ __forceinline__ void f2unpack(unsigned long long v, float &lo, float &hi) {
    asm("mov.b64 {%0, %1}, %2;" : "=f"(lo), "=f"(hi) : "l"(v));
}
__device__ __forceinline__ unsigned long long f2fma(unsigned long long a,
                                                   unsigned long long b,
                                                   unsigned long long c) {
    unsigned long long d;
    asm("fma.rn.f32x2 %0, %1, %2, %3;" : "=l"(d) : "l"(a), "l"(b), "l"(c));
    return d;
}

// ============================================================================
// Fused init: params + Adam state (block 0) AND cursor zeroing (all blocks).
// ============================================================================
__global__ void rmi_init_zero(const float* __restrict__ w1,
                              const float* __restrict__ b1,
                              const float* __restrict__ w2,
                              const float* __restrict__ b2) {
    int gid = blockIdx.x * blockDim.x + threadIdx.x;
    int tot = NSEG * NBKT * CPAD;
    for (int i = gid; i < tot; i += gridDim.x * blockDim.x) {
        g_cursor[0][i] = 0; g_cursor[1][i] = 0;
    }
    if (blockIdx.x == 0) {
        int t = threadIdx.x;
        if (t < 64)       g_P[t] = w1[t];
        else if (t < 68)  g_P[t] = b1[t - 64];
        else if (t < 72)  g_P[t] = w2[t - 68];
        else if (t == 72) g_P[72] = b2[0];
        if (t < 73) { g_m[t] = 0.f; g_v[t] = 0.f; }
    }
}

// ============================================================================
// Permutation pipeline. Payload is now POSITION ONLY (4B); the key is
// regenerated from pos inside bucket_sort (threefry is cheap, bandwidth isn't).
// ============================================================================
__global__ void __launch_bounds__(SCAT_T)
rmi_scatter(SubKeys sk, int N, int cps, int round) {
    int s = blockIdx.x / cps, c = blockIdx.x % cps;
    unsigned* cursor = &g_cursor[round][s * NBKT * CPAD];
    int p0 = c * CHUNK;
#pragma unroll
    for (int j = 0; j < SCAT_I; j++) {
        int p = p0 + j * SCAT_T + threadIdx.x;
        if (p < N) {
            unsigned bb = rnd_bits(sk, s, (unsigned)p);
            unsigned b  = bb >> LOWBITS;
            unsigned slot = atomicAdd(&cursor[b * CPAD], 1u);
            if (slot < CAPR)    // overflow P ~ 1e-20; clamped on read too
                g_pay[((size_t)(s * NBKT + b)) * CAPR + slot] = (unsigned)p;
        }
    }
}

// One block per segment: exclusive scan of 2048 bucket counts -> absolute bases.
__global__ void __launch_bounds__(1024)
rmi_scan(int N, int round) {
    int s = blockIdx.x, t = threadIdx.x;
    const unsigned* cur = &g_cursor[round][s * NBKT * CPAD];
    unsigned c0 = cur[(2 * t) * CPAD],     n0 = c0 > CAPR ? CAPR : c0;
    unsigned c1 = cur[(2 * t + 1) * CPAD], n1 = c1 > CAPR ? CAPR : c1;
    unsigned tsum = n0 + n1;

    int lane = t & 31, w = t >> 5;
    unsigned v = tsum;
#pragma unroll
    for (int o = 1; o < 32; o <<= 1) {
        unsigned u = __shfl_up_sync(0xffffffffu, v, o);
        if (lane >= o) v += u;
    }
    __shared__ unsigned wsums[32];
    if (lane == 31) wsums[w] = v;
    __syncthreads();
    if (w == 0) {
        unsigned x = wsums[lane];
#pragma unroll
        for (int o = 1; o < 32; o <<= 1) {
            unsigned u = __shfl_up_sync(0xffffffffu, x, o);
            if (lane >= o) x += u;
        }
        wsums[lane] = x - wsums[lane];   // exclusive warp offsets
    }
    __syncthreads();
    unsigned excl = wsums[w] + (v - tsum) + (unsigned)(s * N);
    g_base[round][s * NBKT + 2 * t]     = excl;
    g_base[round][s * NBKT + 2 * t + 1] = excl + n0;
}

// ============================================================================
// In-bucket sort: regenerate key from pos; counting sort by key bits [13,21)
// into 256 sub-buckets, serial insertion sort per run on the unique 34-bit
// residue (rem13 key, pos21). Unique residues -> exact stable (key,pos) order.
// ============================================================================
template <int ROUND>
__global__ void __launch_bounds__(SORT_T)
rmi_bucket_sort(SubKeys sk, int N, unsigned* __restrict__ out) {
    int s = blockIdx.x >> BBITS, b = blockIdx.x & (NBKT - 1);
    int sb = s * NBKT + b;
    unsigned n = g_cursor[ROUND][sb * CPAD];
    if (n > CAPR) n = CAPR;
    unsigned base = g_base[ROUND][sb];

    __shared__ unsigned long long buf[CAPF];   // 6 KB
    __shared__ unsigned cnt[NSUB];
    __shared__ unsigned off[NSUB];
    __shared__ unsigned cur[NSUB];
    __shared__ unsigned ws4[4];

    const int tid = threadIdx.x;
    for (int i = tid; i < NSUB; i += SORT_T) cnt[i] = 0;
    __syncthreads();

    // load positions (coalesced), regenerate keys, count sub-buckets
    const unsigned* pay = &g_pay[(size_t)sb * CAPR];
    unsigned long long v[SORT_I];
#pragma unroll
    for (int k = 0; k < SORT_I; k++) {
        unsigned r = (unsigned)(k * SORT_T + tid);
        if (r < n) {
            unsigned pos = pay[r];
            unsigned key = rnd_bits(sk, s, pos) & LOWMASK;
            v[k] = ((unsigned long long)key << POSBITS) | (unsigned long long)pos;
            atomicAdd(&cnt[(unsigned)(v[k] >> 34)], 1u);
        } else v[k] = ~0ull;
    }
    __syncthreads();

    // exclusive scan of 256 counts (2 per thread, shuffle + 4-warp combine)
    {
        unsigned a0 = cnt[2 * tid], a1 = cnt[2 * tid + 1];
        unsigned tsum = a0 + a1;
        int lane = tid & 31, w = tid >> 5;
        unsigned sv = tsum;
#pragma unroll
        for (int o = 1; o < 32; o <<= 1) {
            unsigned u = __shfl_up_sync(0xffffffffu, sv, o);
            if (lane >= o) sv += u;
        }
        if (lane == 31) ws4[w] = sv;
        __syncthreads();
        unsigned wo = 0;
        for (int w2 = 0; w2 < 4; w2++) if (w2 < w) wo += ws4[w2];
        unsigned excl = wo + sv - tsum;
        off[2 * tid] = excl;          cur[2 * tid] = excl;
        off[2 * tid + 1] = excl + a0; cur[2 * tid + 1] = excl + a0;
    }
    __syncthreads();

    // scatter 34-bit residues into sub-bucket runs
#pragma unroll
    for (int k = 0; k < SORT_I; k++) {
        unsigned r = (unsigned)(k * SORT_T + tid);
        if (r < n) {
            unsigned sub = (unsigned)(v[k] >> 34);
            unsigned slot = atomicAdd(&cur[sub], 1u);
            buf[slot] = v[k] & M34;
        }
    }
    __syncthreads();

    // serial insertion sort per run (avg len 3; unique values -> exact order)
    for (int sub = tid; sub < NSUB; sub += SORT_T) {
        unsigned b0 = off[sub], L = cnt[sub];
        for (unsigned i = 1; i < L; i++) {
            unsigned long long key = buf[b0 + i];
            int j = (int)i - 1;
            while (j >= 0 && buf[b0 + j] > key) {
                buf[b0 + j + 1] = buf[b0 + j];
                j--;
            }
            buf[b0 + j + 1] = key;
        }
    }
    __syncthreads();

    // emit permuted values
    for (unsigned r = tid; r < n; r += SORT_T) {
        unsigned pos = (unsigned)buf[r] & POSMASK;
        unsigned val = (ROUND == 0) ? pos : __ldg(&g_v1[s * N + pos]);
        out[base + r] = val;
    }
}

// ============================================================================
// Tiny-MLP helpers
// ============================================================================
__device__ __forceinline__ void load8p(const float* __restrict__ base, unsigned row,
                                       unsigned long long* __restrict__ dst) {
    const float4* p = (const float4*)base + 2ull * row;
    float4 a = __ldg(p), b = __ldg(p + 1);
    dst[0] = f2pack(a.x, a.y); dst[1] = f2pack(a.z, a.w);
    dst[2] = f2pack(b.x, b.y); dst[3] = f2pack(b.z, b.w);
}

__device__ __forceinline__ float ftanh(float x) {
    float e = __expf(2.f * x);
    return 1.f - 2.f * __frcp_rn(e + 1.f);
}

// ============================================================================
// Fused per-step pass — f32x2 packed math. Forward dot (64 FMA -> 32 FFMA2)
// and backward outer product (64 FMA -> 32 FFMA2). Weights + accumulators in
// register pairs; ~175 regs, no min-blocks cap -> no spill.
// ============================================================================
__global__ void __launch_bounds__(GNT)
rmi_fused_step(const float* __restrict__ x, const float* __restrict__ y,
               const unsigned* __restrict__ pi, int N) {
    const int role = blockIdx.x & 1;
    const int b    = blockIdx.x >> 1;
    const int stride = HALFB * GNT;

    __shared__ float Ps[73];
    if (threadIdx.x < 73) Ps[threadIdx.x] = g_P[threadIdx.x];
    __syncthreads();

    // loop-invariant weights in registers
    unsigned long long W2[4][8];
    float B1[4], Wo[4];
#pragma unroll
    for (int k = 0; k < 4; k++) {
#pragma unroll
        for (int j2 = 0; j2 < 8; j2++)
            W2[k][j2] = f2pack(Ps[k * 16 + 2 * j2], Ps[k * 16 + 2 * j2 + 1]);
        B1[k] = Ps[64 + k];
        Wo[k] = Ps[68 + k];
    }
    const float B2 = Ps[72];

    unsigned long long accw[4][8];
#pragma unroll
    for (int k = 0; k < 4; k++)
#pragma unroll
        for (int j2 = 0; j2 < 8; j2++) accw[k][j2] = 0ull;
    float accb1[4] = {0.f, 0.f, 0.f, 0.f};
    float accwo[4] = {0.f, 0.f, 0.f, 0.f};
    float accb2 = 0.f, S = 0.f;

    int i0 = b * GNT + threadIdx.x;
    unsigned rown = 0;
    if (i0 < N) rown = role ? __ldg(pi + i0) : (unsigned)i0;

    for (int i = i0; i < N; i += stride) {
        unsigned row = rown;
        int inx = i + stride;
        if (inx < N) rown = role ? __ldg(pi + inx) : (unsigned)inx;

        unsigned long long in2[8];
        load8p(x, (unsigned)i, in2);
        load8p(y, row, in2 + 4);

        // ---- forward (packed) ----
        float h[4];
        float s = B2;
#pragma unroll
        for (int k = 0; k < 4; k++) {
            unsigned long long u2 = 0ull;
#pragma unroll
            for (int j2 = 0; j2 < 8; j2++) u2 = f2fma(W2[k][j2], in2[j2], u2);
            float ulo, uhi;
            f2unpack(u2, ulo, uhi);
            float hk = ftanh(B1[k] + ulo + uhi);
            h[k] = hk;
            s = fmaf(Wo[k], hk, s);
        }
        float o = ftanh(s);
        float f = role ? 2.f * o : o;       // ALPHA=2: f2 = 2*est, f1 = est
        float w = __expf(f);                // no shift needed: |f| <= 2
        S += w;

        // ---- backward (packed outer product) ----
        float d = w * (1.f - o * o);
        accb2 += d;
#pragma unroll
        for (int k = 0; k < 4; k++) {
            accwo[k] = fmaf(d, h[k], accwo[k]);
            float e = d * Wo[k] * (1.f - h[k] * h[k]);
            accb1[k] += e;
            unsigned long long e2 = f2pack(e, e);
#pragma unroll
            for (int j2 = 0; j2 < 8; j2++)
                accw[k][j2] = f2fma(e2, in2[j2], accw[k][j2]);
        }
    }

    // unpack to canonical 73-float layout
    float acc[73];
#pragma unroll
    for (int k = 0; k < 4; k++) {
#pragma unroll
        for (int j2 = 0; j2 < 8; j2++)
            f2unpack(accw[k][j2], acc[k * 16 + 2 * j2], acc[k * 16 + 2 * j2 + 1]);
        acc[64 + k] = accb1[k];
        acc[68 + k] = accwo[k];
    }
    acc[72] = accb2;

    // --- deterministic block reduction of 73 accumulators ---
#pragma unroll
    for (int t = 0; t < 73; t++) {
        float v = acc[t];
#pragma unroll
        for (int o = 16; o > 0; o >>= 1) v += __shfl_down_sync(0xffffffffu, v, o);
        acc[t] = v;
    }
    __shared__ float wsum[GNT / 32][73];
    int wid = threadIdx.x >> 5, lane = threadIdx.x & 31;
    if (lane == 0) {
#pragma unroll
        for (int t = 0; t < 73; t++) wsum[wid][t] = acc[t];
    }
    __syncthreads();
    if (threadIdx.x < 73) {
        float s = 0.f;
#pragma unroll
        for (int w = 0; w < GNT / 32; w++) s += wsum[w][threadIdx.x];
        g_partial[role][threadIdx.x][b] = s;
    }

    // --- deterministic block reduction of S (fp64 tree) ---
    __shared__ double red[GNT];
    red[threadIdx.x] = (double)S;
    __syncthreads();
    for (int o = GNT / 2; o > 0; o >>= 1) {
        if (threadIdx.x < (unsigned)o) red[threadIdx.x] += red[threadIdx.x + o];
        __syncthreads();
    }
    if (threadIdx.x == 0) g_S[role][b] = red[0];
}

// ============================================================================
// Parallel reduction: 148 blocks (frozen from R12 passer)
// ============================================================================
__global__ void __launch_bounds__(256)
rmi_reduce(void) {
    int row = blockIdx.x, t = threadIdx.x;
    __shared__ double red[256];
    double s = 0.0;
    if (row < 146) {
        int role = row >= 73 ? 1 : 0;
        int p = role ? row - 73 : row;
        const float* src = &g_partial[role][p][0];
        for (int bb = t; bb < HALFB; bb += 256) s += (double)__ldg(src + bb);
    } else {
        int role = row - 146;
        for (int bb = t; bb < HALFB; bb += 256) s += g_S[role][bb];
    }
    red[t] = s;
    __syncthreads();
    for (int o = 128; o > 0; o >>= 1) {
        if (t < o) red[t] += red[t + o];
        __syncthreads();
    }
    if (t == 0) {
        if (row < 146) {
            int role = row >= 73 ? 1 : 0;
            int p = role ? row - 73 : row;
            g_G[role][p] = red[0];
        } else {
            g_Stot[row - 146] = red[0];
        }
    }
}

// ============================================================================
// Adam + loss (frozen)
// ============================================================================
__global__ void __launch_bounds__(128)
rmi_adam(int step, float bc1, float bc2, double logN) {
    double S1 = g_Stot[0], S2 = g_Stot[1];
    if (threadIdx.x == 0) {
        double t1 = log(S1) - logN;              // lse(f1) - logN
        double t2 = 0.5 * (log(S2) - logN);      // (lse(f2) - logN)/ALPHA
        g_losses[step] = (float)(t1 - t2);
    }
    if (threadIdx.x < 73) {
        int t = threadIdx.x;
        float g = (float)(g_G[1][t] / S2 - g_G[0][t] / S1);
        float m = 0.9f   * g_m[t] + 0.1f   * g;
        float v = 0.999f * g_v[t] + 0.001f * g * g;
        g_m[t] = m; g_v[t] = v;
        g_P[t] -= 1e-3f * (m / bc1) / (sqrtf(v / bc2) + 1e-8f);
    }
}

__global__ void rmi_write_out(float* __restrict__ out, int out_size) {
    for (int i = threadIdx.x; i < out_size; i += blockDim.x) {
        float v;
        if (out_size == NSTEPS)      v = g_losses[i];
        else if (out_size == 1)      v = g_losses[NSTEPS - 1];
        else {
            if (i == 0)              v = g_losses[NSTEPS - 1];
            else if (i <= NSTEPS)    v = g_losses[i - 1];
            else                     v = 0.f;
        }
        out[i] = v;
    }
}

// ============================================================================
// Host driver (graph-capturable: plain kernel launches only)
// ============================================================================
extern "C" void kernel_launch(void* const* d_in, const int* in_sizes, int n_in,
                              void* d_out, int out_size) {
    const float* x  = (const float*)d_in[0];
    const float* y  = (const float*)d_in[1];
    const float* w1 = (const float*)d_in[2];
    const float* b1 = (const float*)d_in[3];
    const float* w2 = (const float*)d_in[4];
    const float* b2 = (const float*)d_in[5];
    int N = in_sizes[0] / 8;
    if (N > MAXN) N = MAXN;

    // --- shuffle subkeys (host, input-independent, deterministic) ---
    // master key(42) = (0,42); fold-like split: key_s = tf(master,(0,s));
    // per round: new_key = tf(K,(0,0)), subkey = tf(K,(0,1)). 2 rounds for
    // N ~ 1M (ceil(3*log(N)/log(2^32)) = 2).
    SubKeys subk[2];
    for (int s = 0; s < NSEG; s++) {
        unsigned K0, K1;
        tf2x32(0u, 42u, 0u, (unsigned)s, K0, K1);
        for (int r = 0; r < 2; r++) {
            unsigned nk0, nk1, sb0, sb1;
            tf2x32(K0, K1, 0u, 0u, nk0, nk1);
            tf2x32(K0, K1, 0u, 1u, sb0, sb1);
            subk[r].k0[s] = sb0; subk[r].k1[s] = sb1;
            K0 = nk0; K1 = nk1;
        }
    }

    unsigned *v1p, *pp;
    cudaGetSymbolAddress((void**)&v1p, g_v1);
    cudaGetSymbolAddress((void**)&pp, g_perms);

    // --- launches: index 3 == bucket_sort<0> (the profiler's capture slot) ---
    const int cps = (N + CHUNK - 1) / CHUNK;
    rmi_init_zero<<<64, 512>>>(w1, b1, w2, b2);                       // 0
    rmi_scatter<<<NSEG * cps, SCAT_T>>>(subk[0], N, cps, 0);          // 1
    rmi_scan<<<NSEG, 1024>>>(N, 0);                                   // 2
    rmi_bucket_sort<0><<<NSEG << BBITS, SORT_T>>>(subk[0], N, v1p);   // 3  <- profiled
    rmi_scatter<<<NSEG * cps, SCAT_T>>>(subk[1], N, cps, 1);          // 4
    rmi_scan<<<NSEG, 1024>>>(N, 1);                                   // 5
    rmi_bucket_sort<1><<<NSEG << BBITS, SORT_T>>>(subk[1], N, pp);    // 6

    // --- 8 fused training steps ---
    const double logN = log((double)N);
    for (int s = 0; s < NSTEPS; s++) {
        const unsigned* pi = pp + (size_t)s * N;
        rmi_fused_step<<<2 * HALFB, GNT>>>(x, y, pi, N);
        rmi_reduce<<<148, 256>>>();
        double t = (double)(s + 1);
        float bc1 = (float)(1.0 - pow(0.9,   t));
        float bc2 = (float)(1.0 - pow(0.999, t));
        rmi_adam<<<1, 128>>>(s, bc1, bc2, logN);
    }

    rmi_write_out<<<1, 32>>>((float*)d_out, out_size);
}

// round 14
// speedup vs baseline: 1.3601x; 1.3601x over previous
#include <cuda_runtime.h>
#include <cstdint>
#include <math.h>

// ============================================================================
// Problem constants
// ============================================================================
#define MAXN    1048576
#define NSTEPS  8
#define NSEG    8               // 8 permutations (one per training step)
#define HALFB   296             // blocks per role; grid = 592 = 148 SMs x 4 CTAs (1 wave)
#define GNT     128             // threads per block in step kernel

// --- permutation sort configuration ---
#define BBITS   11              // MSD bucket bits
#define NBKT    (1 << BBITS)    // 2048 buckets per segment
#define LOWBITS (32 - BBITS)    // 21 low key bits
#define LOWMASK ((1u << LOWBITS) - 1u)
#define POSBITS 21              // position field (N <= 2^20)
#define POSMASK ((1u << POSBITS) - 1u)
#define CAPR    768             // fixed region capacity (avg 512, +11 sigma)
#define SORT_T  128
#define SORT_I  6               // 128*6 = 768 = CAPR
#define CAPF    (SORT_T * SORT_I)
#define SUBB    8               // in-bucket counting-sort bits (key bits [13,21))
#define NSUB    (1 << SUBB)     // 256 sub-buckets, avg 3 elements each
#define M34     ((1ull << 34) - 1ull)   // residue: (rem13 key << 21) | pos
#define SCAT_T  512
#define SCAT_I  16
#define CHUNK   (SCAT_T * SCAT_I)   // 8192 elements per scatter CTA
#define CPAD    8               // cursor padding (32B stride)

struct SubKeys { unsigned k0[NSEG]; unsigned k1[NSEG]; };

// ============================================================================
// Static device scratch (no dynamic allocation allowed)
// ============================================================================
__device__ __align__(256) unsigned long long g_pay[NSEG * NBKT * (size_t)CAPR]; // (low21key<<21)|pos
__device__ __align__(256) unsigned g_v1[NSEG * MAXN];    // round-1 result
__device__ __align__(256) unsigned g_perms[NSEG * MAXN]; // final permutations
__device__ unsigned g_cursor[2][NSEG * NBKT * CPAD];
__device__ unsigned g_base[2][NSEG * NBKT];

__device__ float  g_P[73];                    // [0..63]=w1, [64..67]=b1, [68..71]=w2, [72]=b2
__device__ float  g_m[73];
__device__ float  g_v[73];
__device__ float  g_partial[2][73][HALFB];
__device__ double g_S[2][HALFB];
__device__ double g_G[2][73];
__device__ double g_Stot[2];
__device__ float  g_losses[NSTEPS];

// ============================================================================
// Threefry2x32 — exact JAX implementation
// ============================================================================
__host__ __device__ __forceinline__ void tf2x32(unsigned k0, unsigned k1,
                                                unsigned c0, unsigned c1,
                                                unsigned &o0, unsigned &o1) {
    unsigned ks0 = k0, ks1 = k1, ks2 = k0 ^ k1 ^ 0x1BD11BDAu;
    unsigned x0 = c0 + ks0, x1 = c1 + ks1;
#define TFR(r) { x0 += x1; x1 = (x1 << (r)) | (x1 >> (32 - (r))); x1 ^= x0; }
    TFR(13) TFR(15) TFR(26) TFR(6)
    x0 += ks1; x1 += ks2 + 1u;
    TFR(17) TFR(29) TFR(16) TFR(24)
    x0 += ks2; x1 += ks0 + 2u;
    TFR(13) TFR(15) TFR(26) TFR(6)
    x0 += ks0; x1 += ks1 + 3u;
    TFR(17) TFR(29) TFR(16) TFR(24)
    x0 += ks1; x1 += ks2 + 4u;
    TFR(13) TFR(15) TFR(26) TFR(6)
    x0 += ks2; x1 += ks0 + 5u;
#undef TFR
    o0 = x0; o1 = x1;
}

__device__ __forceinline__ unsigned rnd_bits(const SubKeys& sk, int s, unsigned p) {
    unsigned a, b;
    tf2x32(sk.k0[s], sk.k1[s], 0u, p, a, b);
    return a ^ b;   // partitionable-threefry 32-bit random_bits
}

// ============================================================================
// Fused init: params + Adam state (block 0) AND cursor zeroing (all blocks).
// ============================================================================
__global__ void rmi_init_zero(const float* __restrict__ w1,
                              const float* __restrict__ b1,
                              const float* __restrict__ w2,
                              const float* __restrict__ b2) {
    int gid = blockIdx.x * blockDim.x + threadIdx.x;
    int tot = NSEG * NBKT * CPAD;
    for (int i = gid; i < tot; i += gridDim.x * blockDim.x) {
        g_cursor[0][i] = 0; g_cursor[1][i] = 0;
    }
    if (blockIdx.x == 0) {
        int t = threadIdx.x;
        if (t < 64)       g_P[t] = w1[t];
        else if (t < 68)  g_P[t] = b1[t - 64];
        else if (t < 72)  g_P[t] = w2[t - 68];
        else if (t == 72) g_P[72] = b2[0];
        if (t < 73) { g_m[t] = 0.f; g_v[t] = 0.f; }
    }
}

// ============================================================================
// Permutation pipeline (R12 form: 8-byte payload (low21key, pos); no key regen)
// ============================================================================
__global__ void __launch_bounds__(SCAT_T)
rmi_scatter(SubKeys sk, int N, int cps, int round) {
    int s = blockIdx.x / cps, c = blockIdx.x % cps;
    unsigned* cursor = &g_cursor[round][s * NBKT * CPAD];
    int p0 = c * CHUNK;
#pragma unroll
    for (int j = 0; j < SCAT_I; j++) {
        int p = p0 + j * SCAT_T + threadIdx.x;
        if (p < N) {
            unsigned bb = rnd_bits(sk, s, (unsigned)p);
            unsigned b  = bb >> LOWBITS;
            unsigned slot = atomicAdd(&cursor[b * CPAD], 1u);
            if (slot < CAPR)    // overflow P ~ 1e-20; clamped on read too
                g_pay[((size_t)(s * NBKT + b)) * CAPR + slot] =
                    ((unsigned long long)(bb & LOWMASK) << POSBITS)
                  | (unsigned long long)(unsigned)p;
        }
    }
}

// One block per segment: exclusive scan of 2048 bucket counts -> absolute bases.
__global__ void __launch_bounds__(1024)
rmi_scan(int N, int round) {
    int s = blockIdx.x, t = threadIdx.x;
    const unsigned* cur = &g_cursor[round][s * NBKT * CPAD];
    unsigned c0 = cur[(2 * t) * CPAD],     n0 = c0 > CAPR ? CAPR : c0;
    unsigned c1 = cur[(2 * t + 1) * CPAD], n1 = c1 > CAPR ? CAPR : c1;
    unsigned tsum = n0 + n1;

    int lane = t & 31, w = t >> 5;
    unsigned v = tsum;
#pragma unroll
    for (int o = 1; o < 32; o <<= 1) {
        unsigned u = __shfl_up_sync(0xffffffffu, v, o);
        if (lane >= o) v += u;
    }
    __shared__ unsigned wsums[32];
    if (lane == 31) wsums[w] = v;
    __syncthreads();
    if (w == 0) {
        unsigned x = wsums[lane];
#pragma unroll
        for (int o = 1; o < 32; o <<= 1) {
            unsigned u = __shfl_up_sync(0xffffffffu, x, o);
            if (lane >= o) x += u;
        }
        wsums[lane] = x - wsums[lane];   // exclusive warp offsets
    }
    __syncthreads();
    unsigned excl = wsums[w] + (v - tsum) + (unsigned)(s * N);
    g_base[round][s * NBKT + 2 * t]     = excl;
    g_base[round][s * NBKT + 2 * t + 1] = excl + n0;
}

// ============================================================================
// In-bucket sort (R12 form): counting sort by key bits [13,21) into 256
// sub-buckets, serial insertion sort per run on the unique 34-bit residue
// (rem13 key, pos21). Unique residues -> exact stable (key,pos) order.
// ============================================================================
template <int ROUND>
__global__ void __launch_bounds__(SORT_T)
rmi_bucket_sort(int N, unsigned* __restrict__ out) {
    int s = blockIdx.x >> BBITS, b = blockIdx.x & (NBKT - 1);
    int sb = s * NBKT + b;
    unsigned n = g_cursor[ROUND][sb * CPAD];
    if (n > CAPR) n = CAPR;
    unsigned base = g_base[ROUND][sb];

    __shared__ unsigned long long buf[CAPF];   // 6 KB
    __shared__ unsigned cnt[NSUB];
    __shared__ unsigned off[NSUB];
    __shared__ unsigned cur[NSUB];
    __shared__ unsigned ws4[4];

    const int tid = threadIdx.x;
    for (int i = tid; i < NSUB; i += SORT_T) cnt[i] = 0;
    __syncthreads();

    // load payloads (coalesced over filled region) + count sub-buckets
    const unsigned long long* pay = &g_pay[(size_t)sb * CAPR];
    unsigned long long v[SORT_I];
#pragma unroll
    for (int k = 0; k < SORT_I; k++) {
        unsigned r = (unsigned)(k * SORT_T + tid);
        if (r < n) {
            v[k] = pay[r];
            atomicAdd(&cnt[(unsigned)(v[k] >> 34)], 1u);
        } else v[k] = ~0ull;
    }
    __syncthreads();

    // exclusive scan of 256 counts (2 per thread, shuffle + 4-warp combine)
    {
        unsigned a0 = cnt[2 * tid], a1 = cnt[2 * tid + 1];
        unsigned tsum = a0 + a1;
        int lane = tid & 31, w = tid >> 5;
        unsigned sv = tsum;
#pragma unroll
        for (int o = 1; o < 32; o <<= 1) {
            unsigned u = __shfl_up_sync(0xffffffffu, sv, o);
            if (lane >= o) sv += u;
        }
        if (lane == 31) ws4[w] = sv;
        __syncthreads();
        unsigned wo = 0;
        for (int w2 = 0; w2 < 4; w2++) if (w2 < w) wo += ws4[w2];
        unsigned excl = wo + sv - tsum;
        off[2 * tid] = excl;          cur[2 * tid] = excl;
        off[2 * tid + 1] = excl + a0; cur[2 * tid + 1] = excl + a0;
    }
    __syncthreads();

    // scatter 34-bit residues into sub-bucket runs
#pragma unroll
    for (int k = 0; k < SORT_I; k++) {
        unsigned r = (unsigned)(k * SORT_T + tid);
        if (r < n) {
            unsigned sub = (unsigned)(v[k] >> 34);
            unsigned slot = atomicAdd(&cur[sub], 1u);
            buf[slot] = v[k] & M34;
        }
    }
    __syncthreads();

    // serial insertion sort per run (avg len 3; unique values -> exact order)
    for (int sub = tid; sub < NSUB; sub += SORT_T) {
        unsigned b0 = off[sub], L = cnt[sub];
        for (unsigned i = 1; i < L; i++) {
            unsigned long long key = buf[b0 + i];
            int j = (int)i - 1;
            while (j >= 0 && buf[b0 + j] > key) {
                buf[b0 + j + 1] = buf[b0 + j];
                j--;
            }
            buf[b0 + j + 1] = key;
        }
    }
    __syncthreads();

    // emit permuted values
    for (unsigned r = tid; r < n; r += SORT_T) {
        unsigned pos = (unsigned)buf[r] & POSMASK;
        unsigned val = (ROUND == 0) ? pos : __ldg(&g_v1[s * N + pos]);
        out[base + r] = val;
    }
}

// ============================================================================
// Tiny-MLP helpers
// ============================================================================
__device__ __forceinline__ void load8(const float* __restrict__ base, unsigned row,
                                      float* __restrict__ dst) {
    const float4* p = (const float4*)base + 2ull * row;
    float4 a = __ldg(p), b = __ldg(p + 1);
    dst[0] = a.x; dst[1] = a.y; dst[2] = a.z; dst[3] = a.w;
    dst[4] = b.x; dst[5] = b.y; dst[6] = b.z; dst[7] = b.w;
}

__device__ __forceinline__ float ftanh(float x) {
    float e = __expf(2.f * x);
    return 1.f - 2.f * __frcp_rn(e + 1.f);
}

// ============================================================================
// Fused per-step pass — scalar minimal-register variant (R11/R12 passer),
// now at grid 2*296 = 592 CTAs = exactly one wave at 4 CTAs/SM.
// ============================================================================
__global__ void __launch_bounds__(GNT)
rmi_fused_step(const float* __restrict__ x, const float* __restrict__ y,
               const unsigned* __restrict__ pi, int N) {
    const int role = blockIdx.x & 1;
    const int b    = blockIdx.x >> 1;
    const int stride = HALFB * GNT;

    __shared__ float Ps[73];
    if (threadIdx.x < 73) Ps[threadIdx.x] = g_P[threadIdx.x];
    __syncthreads();

    float acc[73];
#pragma unroll
    for (int t = 0; t < 73; t++) acc[t] = 0.f;
    float S = 0.f;

    int i0 = b * GNT + threadIdx.x;
    unsigned rown = 0;
    if (i0 < N) rown = role ? __ldg(pi + i0) : (unsigned)i0;

    for (int i = i0; i < N; i += stride) {
        unsigned row = rown;
        int inx = i + stride;
        if (inx < N) rown = role ? __ldg(pi + inx) : (unsigned)inx;

        float inp[16];
        load8(x, (unsigned)i, inp);
        load8(y, row, inp + 8);

        float h[4];
        float s = Ps[72];
#pragma unroll
        for (int k = 0; k < 4; k++) {
            float u = Ps[64 + k];
#pragma unroll
            for (int j = 0; j < 16; j++) u = fmaf(Ps[k * 16 + j], inp[j], u);
            float hk = ftanh(u);
            h[k] = hk;
            s = fmaf(Ps[68 + k], hk, s);
        }
        float o = ftanh(s);
        float f = role ? 2.f * o : o;       // ALPHA=2: f2 = 2*est, f1 = est
        float w = __expf(f);                // no shift needed: |f| <= 2
        S += w;

        float d = w * (1.f - o * o);
        acc[72] += d;
#pragma unroll
        for (int k = 0; k < 4; k++) {
            acc[68 + k] = fmaf(d, h[k], acc[68 + k]);
            float e = d * Ps[68 + k] * (1.f - h[k] * h[k]);
            acc[64 + k] += e;
#pragma unroll
            for (int j = 0; j < 16; j++)
                acc[k * 16 + j] = fmaf(e, inp[j], acc[k * 16 + j]);
        }
    }

    // --- deterministic block reduction of 73 accumulators ---
#pragma unroll
    for (int t = 0; t < 73; t++) {
        float v = acc[t];
#pragma unroll
        for (int o = 16; o > 0; o >>= 1) v += __shfl_down_sync(0xffffffffu, v, o);
        acc[t] = v;
    }
    __shared__ float wsum[GNT / 32][73];
    int wid = threadIdx.x >> 5, lane = threadIdx.x & 31;
    if (lane == 0) {
#pragma unroll
        for (int t = 0; t < 73; t++) wsum[wid][t] = acc[t];
    }
    __syncthreads();
    if (threadIdx.x < 73) {
        float s = 0.f;
#pragma unroll
        for (int w = 0; w < GNT / 32; w++) s += wsum[w][threadIdx.x];
        g_partial[role][threadIdx.x][b] = s;
    }

    // --- deterministic block reduction of S (fp64 tree) ---
    __shared__ double red[GNT];
    red[threadIdx.x] = (double)S;
    __syncthreads();
    for (int o = GNT / 2; o > 0; o >>= 1) {
        if (threadIdx.x < (unsigned)o) red[threadIdx.x] += red[threadIdx.x + o];
        __syncthreads();
    }
    if (threadIdx.x == 0) g_S[role][b] = red[0];
}

// ============================================================================
// Parallel reduction: 148 blocks (rows 0..145 grads, 146/147 S sums)
// ============================================================================
__global__ void __launch_bounds__(256)
rmi_reduce(void) {
    int row = blockIdx.x, t = threadIdx.x;
    __shared__ double red[256];
    double s = 0.0;
    if (row < 146) {
        int role = row >= 73 ? 1 : 0;
        int p = role ? row - 73 : row;
        const float* src = &g_partial[role][p][0];
        for (int bb = t; bb < HALFB; bb += 256) s += (double)__ldg(src + bb);
    } else {
        int role = row - 146;
        for (int bb = t; bb < HALFB; bb += 256) s += g_S[role][bb];
    }
    red[t] = s;
    __syncthreads();
    for (int o = 128; o > 0; o >>= 1) {
        if (t < o) red[t] += red[t + o];
        __syncthreads();
    }
    if (t == 0) {
        if (row < 146) {
            int role = row >= 73 ? 1 : 0;
            int p = role ? row - 73 : row;
            g_G[role][p] = red[0];
        } else {
            g_Stot[row - 146] = red[0];
        }
    }
}

// ============================================================================
// Adam + loss (frozen)
// ============================================================================
__global__ void __launch_bounds__(128)
rmi_adam(int step, float bc1, float bc2, double logN) {
    double S1 = g_Stot[0], S2 = g_Stot[1];
    if (threadIdx.x == 0) {
        double t1 = log(S1) - logN;              // lse(f1) - logN
        double t2 = 0.5 * (log(S2) - logN);      // (lse(f2) - logN)/ALPHA
        g_losses[step] = (float)(t1 - t2);
    }
    if (threadIdx.x < 73) {
        int t = threadIdx.x;
        float g = (float)(g_G[1][t] / S2 - g_G[0][t] / S1);
        float m = 0.9f   * g_m[t] + 0.1f   * g;
        float v = 0.999f * g_v[t] + 0.001f * g * g;
        g_m[t] = m; g_v[t] = v;
        g_P[t] -= 1e-3f * (m / bc1) / (sqrtf(v / bc2) + 1e-8f);
    }
}

__global__ void rmi_write_out(float* __restrict__ out, int out_size) {
    for (int i = threadIdx.x; i < out_size; i += blockDim.x) {
        float v;
        if (out_size == NSTEPS)      v = g_losses[i];
        else if (out_size == 1)      v = g_losses[NSTEPS - 1];
        else {
            if (i == 0)              v = g_losses[NSTEPS - 1];
            else if (i <= NSTEPS)    v = g_losses[i - 1];
            else                     v = 0.f;
        }
        out[i] = v;
    }
}

// ============================================================================
// Host driver (graph-capturable: plain kernel launches only)
// ============================================================================
extern "C" void kernel_launch(void* const* d_in, const int* in_sizes, int n_in,
                              void* d_out, int out_size) {
    const float* x  = (const float*)d_in[0];
    const float* y  = (const float*)d_in[1];
    const float* w1 = (const float*)d_in[2];
    const float* b1 = (const float*)d_in[3];
    const float* w2 = (const float*)d_in[4];
    const float* b2 = (const float*)d_in[5];
    int N = in_sizes[0] / 8;
    if (N > MAXN) N = MAXN;

    // --- shuffle subkeys (host, input-independent, deterministic) ---
    // master key(42) = (0,42); fold-like split: key_s = tf(master,(0,s));
    // per round: new_key = tf(K,(0,0)), subkey = tf(K,(0,1)). 2 rounds for
    // N ~ 1M (ceil(3*log(N)/log(2^32)) = 2).
    SubKeys subk[2];
    for (int s = 0; s < NSEG; s++) {
        unsigned K0, K1;
        tf2x32(0u, 42u, 0u, (unsigned)s, K0, K1);
        for (int r = 0; r < 2; r++) {
            unsigned nk0, nk1, sb0, sb1;
            tf2x32(K0, K1, 0u, 0u, nk0, nk1);
            tf2x32(K0, K1, 0u, 1u, sb0, sb1);
            subk[r].k0[s] = sb0; subk[r].k1[s] = sb1;
            K0 = nk0; K1 = nk1;
        }
    }

    unsigned *v1p, *pp;
    cudaGetSymbolAddress((void**)&v1p, g_v1);
    cudaGetSymbolAddress((void**)&pp, g_perms);

    // --- launches: index 3 == bucket_sort<0> (the profiler's capture slot) ---
    const int cps = (N + CHUNK - 1) / CHUNK;
    rmi_init_zero<<<64, 512>>>(w1, b1, w2, b2);                 // 0
    rmi_scatter<<<NSEG * cps, SCAT_T>>>(subk[0], N, cps, 0);    // 1
    rmi_scan<<<NSEG, 1024>>>(N, 0);                             // 2
    rmi_bucket_sort<0><<<NSEG << BBITS, SORT_T>>>(N, v1p);      // 3  <- profiled
    rmi_scatter<<<NSEG * cps, SCAT_T>>>(subk[1], N, cps, 1);    // 4
    rmi_scan<<<NSEG, 1024>>>(N, 1);                             // 5
    rmi_bucket_sort<1><<<NSEG << BBITS, SORT_T>>>(N, pp);       // 6

    // --- 8 fused training steps ---
    const double logN = log((double)N);
    for (int s = 0; s < NSTEPS; s++) {
        const unsigned* pi = pp + (size_t)s * N;
        rmi_fused_step<<<2 * HALFB, GNT>>>(x, y, pi, N);
        rmi_reduce<<<148, 256>>>();
        double t = (double)(s + 1);
        float bc1 = (float)(1.0 - pow(0.9,   t));
        float bc2 = (float)(1.0 - pow(0.999, t));
        rmi_adam<<<1, 128>>>(s, bc1, bc2, logN);
    }

    rmi_write_out<<<1, 32>>>((float*)d_out, out_size);
}

// round 15
// speedup vs baseline: 1.4253x; 1.0480x over previous
#include <cuda_runtime.h>
#include <cstdint>
#include <math.h>

// ============================================================================
// Problem constants
// ============================================================================
#define MAXN    1048576
#define NSTEPS  8
#define NSEG    8               // 8 permutations (one per training step)
#define HALFB   296             // blocks per role; grid = 592 = 148 SMs x 4 CTAs (1 wave)
#define GNT     128             // threads per block in step kernel

// --- permutation sort configuration ---
#define BBITS   11              // MSD bucket bits
#define NBKT    (1 << BBITS)    // 2048 buckets per segment
#define LOWBITS (32 - BBITS)    // 21 low key bits
#define LOWMASK ((1u << LOWBITS) - 1u)
#define POSBITS 21              // position field (N <= 2^20)
#define POSMASK ((1u << POSBITS) - 1u)
#define CAPR    768             // fixed region capacity (avg 512, +11 sigma)
#define SORT_T  128
#define SORT_I  6               // 128*6 = 768 = CAPR
#define CAPF    (SORT_T * SORT_I)
#define SUBB    8               // in-bucket counting-sort bits (key bits [13,21))
#define NSUB    (1 << SUBB)     // 256 sub-buckets, avg 3 elements each
#define M34     ((1ull << 34) - 1ull)   // residue: (rem13 key << 21) | pos
#define SCAT_T  512
#define SCAT_I  16
#define CHUNK   (SCAT_T * SCAT_I)   // 8192 elements per scatter CTA
#define CPAD    8               // cursor padding (32B stride)

struct SubKeys { unsigned k0[NSEG]; unsigned k1[NSEG]; };

// ============================================================================
// Static device scratch (no dynamic allocation allowed)
// ============================================================================
__device__ __align__(256) unsigned long long g_pay[NSEG * NBKT * (size_t)CAPR]; // (low21key<<21)|pos
__device__ __align__(256) unsigned g_v1[NSEG * MAXN];    // round-1 result
__device__ __align__(256) unsigned g_perms[NSEG * MAXN]; // final permutations
__device__ unsigned g_cursor[2][NSEG * NBKT * CPAD];
__device__ unsigned g_base[2][NSEG * NBKT];

__device__ float  g_P[73];                    // [0..63]=w1, [64..67]=b1, [68..71]=w2, [72]=b2
__device__ float  g_m[73];
__device__ float  g_v[73];
__device__ float  g_partial[2][73][HALFB];
__device__ double g_S[2][HALFB];
__device__ double g_G[2][73];
__device__ double g_Stot[2];
__device__ float  g_losses[NSTEPS];

// ============================================================================
// Threefry2x32 — exact JAX implementation
// ============================================================================
__host__ __device__ __forceinline__ void tf2x32(unsigned k0, unsigned k1,
                                                unsigned c0, unsigned c1,
                                                unsigned &o0, unsigned &o1) {
    unsigned ks0 = k0, ks1 = k1, ks2 = k0 ^ k1 ^ 0x1BD11BDAu;
    unsigned x0 = c0 + ks0, x1 = c1 + ks1;
#define TFR(r) { x0 += x1; x1 = (x1 << (r)) | (x1 >> (32 - (r))); x1 ^= x0; }
    TFR(13) TFR(15) TFR(26) TFR(6)
    x0 += ks1; x1 += ks2 + 1u;
    TFR(17) TFR(29) TFR(16) TFR(24)
    x0 += ks2; x1 += ks0 + 2u;
    TFR(13) TFR(15) TFR(26) TFR(6)
    x0 += ks0; x1 += ks1 + 3u;
    TFR(17) TFR(29) TFR(16) TFR(24)
    x0 += ks1; x1 += ks2 + 4u;
    TFR(13) TFR(15) TFR(26) TFR(6)
    x0 += ks2; x1 += ks0 + 5u;
#undef TFR
    o0 = x0; o1 = x1;
}

__device__ __forceinline__ unsigned rnd_bits(const SubKeys& sk, int s, unsigned p) {
    unsigned a, b;
    tf2x32(sk.k0[s], sk.k1[s], 0u, p, a, b);
    return a ^ b;   // partitionable-threefry 32-bit random_bits
}

// ============================================================================
// Init, split into 3 launches so the profiler's capture slot lands on
// rmi_scatter (or bucket_sort<0> as a known control, per the skip rule).
// ============================================================================
__global__ void rmi_init_params(const float* __restrict__ w1,
                                const float* __restrict__ b1,
                                const float* __restrict__ w2,
                                const float* __restrict__ b2) {
    int t = threadIdx.x;
    if (t < 64)       g_P[t] = w1[t];
    else if (t < 68)  g_P[t] = b1[t - 64];
    else if (t < 72)  g_P[t] = w2[t - 68];
    else if (t == 72) g_P[72] = b2[0];
    if (t < 73) { g_m[t] = 0.f; g_v[t] = 0.f; }
}

__global__ void rmi_zero_cursors(int round) {
    int gid = blockIdx.x * blockDim.x + threadIdx.x;
    int tot = NSEG * NBKT * CPAD;
    for (int i = gid; i < tot; i += gridDim.x * blockDim.x)
        g_cursor[round][i] = 0;
}

// ============================================================================
// Permutation pipeline (frozen from R14 passer)
// ============================================================================
__global__ void __launch_bounds__(SCAT_T)
rmi_scatter(SubKeys sk, int N, int cps, int round) {
    int s = blockIdx.x / cps, c = blockIdx.x % cps;
    unsigned* cursor = &g_cursor[round][s * NBKT * CPAD];
    int p0 = c * CHUNK;
#pragma unroll
    for (int j = 0; j < SCAT_I; j++) {
        int p = p0 + j * SCAT_T + threadIdx.x;
        if (p < N) {
            unsigned bb = rnd_bits(sk, s, (unsigned)p);
            unsigned b  = bb >> LOWBITS;
            unsigned slot = atomicAdd(&cursor[b * CPAD], 1u);
            if (slot < CAPR)    // overflow P ~ 1e-20; clamped on read too
                g_pay[((size_t)(s * NBKT + b)) * CAPR + slot] =
                    ((unsigned long long)(bb & LOWMASK) << POSBITS)
                  | (unsigned long long)(unsigned)p;
        }
    }
}

// One block per segment: exclusive scan of 2048 bucket counts -> absolute bases.
__global__ void __launch_bounds__(1024)
rmi_scan(int N, int round) {
    int s = blockIdx.x, t = threadIdx.x;
    const unsigned* cur = &g_cursor[round][s * NBKT * CPAD];
    unsigned c0 = cur[(2 * t) * CPAD],     n0 = c0 > CAPR ? CAPR : c0;
    unsigned c1 = cur[(2 * t + 1) * CPAD], n1 = c1 > CAPR ? CAPR : c1;
    unsigned tsum = n0 + n1;

    int lane = t & 31, w = t >> 5;
    unsigned v = tsum;
#pragma unroll
    for (int o = 1; o < 32; o <<= 1) {
        unsigned u = __shfl_up_sync(0xffffffffu, v, o);
        if (lane >= o) v += u;
    }
    __shared__ unsigned wsums[32];
    if (lane == 31) wsums[w] = v;
    __syncthreads();
    if (w == 0) {
        unsigned x = wsums[lane];
#pragma unroll
        for (int o = 1; o < 32; o <<= 1) {
            unsigned u = __shfl_up_sync(0xffffffffu, x, o);
            if (lane >= o) x += u;
        }
        wsums[lane] = x - wsums[lane];   // exclusive warp offsets
    }
    __syncthreads();
    unsigned excl = wsums[w] + (v - tsum) + (unsigned)(s * N);
    g_base[round][s * NBKT + 2 * t]     = excl;
    g_base[round][s * NBKT + 2 * t + 1] = excl + n0;
}

// ============================================================================
// In-bucket sort (frozen from R14 passer)
// ============================================================================
template <int ROUND>
__global__ void __launch_bounds__(SORT_T)
rmi_bucket_sort(int N, unsigned* __restrict__ out) {
    int s = blockIdx.x >> BBITS, b = blockIdx.x & (NBKT - 1);
    int sb = s * NBKT + b;
    unsigned n = g_cursor[ROUND][sb * CPAD];
    if (n > CAPR) n = CAPR;
    unsigned base = g_base[ROUND][sb];

    __shared__ unsigned long long buf[CAPF];   // 6 KB
    __shared__ unsigned cnt[NSUB];
    __shared__ unsigned off[NSUB];
    __shared__ unsigned cur[NSUB];
    __shared__ unsigned ws4[4];

    const int tid = threadIdx.x;
    for (int i = tid; i < NSUB; i += SORT_T) cnt[i] = 0;
    __syncthreads();

    const unsigned long long* pay = &g_pay[(size_t)sb * CAPR];
    unsigned long long v[SORT_I];
#pragma unroll
    for (int k = 0; k < SORT_I; k++) {
        unsigned r = (unsigned)(k * SORT_T + tid);
        if (r < n) {
            v[k] = pay[r];
            atomicAdd(&cnt[(unsigned)(v[k] >> 34)], 1u);
        } else v[k] = ~0ull;
    }
    __syncthreads();

    {
        unsigned a0 = cnt[2 * tid], a1 = cnt[2 * tid + 1];
        unsigned tsum = a0 + a1;
        int lane = tid & 31, w = tid >> 5;
        unsigned sv = tsum;
#pragma unroll
        for (int o = 1; o < 32; o <<= 1) {
            unsigned u = __shfl_up_sync(0xffffffffu, sv, o);
            if (lane >= o) sv += u;
        }
        if (lane == 31) ws4[w] = sv;
        __syncthreads();
        unsigned wo = 0;
        for (int w2 = 0; w2 < 4; w2++) if (w2 < w) wo += ws4[w2];
        unsigned excl = wo + sv - tsum;
        off[2 * tid] = excl;          cur[2 * tid] = excl;
        off[2 * tid + 1] = excl + a0; cur[2 * tid + 1] = excl + a0;
    }
    __syncthreads();

#pragma unroll
    for (int k = 0; k < SORT_I; k++) {
        unsigned r = (unsigned)(k * SORT_T + tid);
        if (r < n) {
            unsigned sub = (unsigned)(v[k] >> 34);
            unsigned slot = atomicAdd(&cur[sub], 1u);
            buf[slot] = v[k] & M34;
        }
    }
    __syncthreads();

    for (int sub = tid; sub < NSUB; sub += SORT_T) {
        unsigned b0 = off[sub], L = cnt[sub];
        for (unsigned i = 1; i < L; i++) {
            unsigned long long key = buf[b0 + i];
            int j = (int)i - 1;
            while (j >= 0 && buf[b0 + j] > key) {
                buf[b0 + j + 1] = buf[b0 + j];
                j--;
            }
            buf[b0 + j + 1] = key;
        }
    }
    __syncthreads();

    for (unsigned r = tid; r < n; r += SORT_T) {
        unsigned pos = (unsigned)buf[r] & POSMASK;
        unsigned val = (ROUND == 0) ? pos : __ldg(&g_v1[s * N + pos]);
        out[base + r] = val;
    }
}

// ============================================================================
// Tiny-MLP helpers
// ============================================================================
__device__ __forceinline__ void load8(const float* __restrict__ base, unsigned row,
                                      float* __restrict__ dst) {
    const float4* p = (const float4*)base + 2ull * row;
    float4 a = __ldg(p), b = __ldg(p + 1);
    dst[0] = a.x; dst[1] = a.y; dst[2] = a.z; dst[3] = a.w;
    dst[4] = b.x; dst[5] = b.y; dst[6] = b.z; dst[7] = b.w;
}

// HW tanh (sm_75+): 1 MUFU op vs 2+ for exp-based. Approx error enters the
// loss only as the mean bias of delta-o, which largely cancels in t1 - t2
// (both terms share the same marginal of o).
__device__ __forceinline__ float ftanh(float x) {
    float r;
    asm("tanh.approx.f32 %0, %1;" : "=f"(r) : "f"(x));
    return r;
}

// ============================================================================
// Fused per-step pass — MUFU-lean: tanh.approx (5 MUFU saved/sample) and
// 2-way split dot products (halved serial FMA chain depth).
// ============================================================================
__global__ void __launch_bounds__(GNT)
rmi_fused_step(const float* __restrict__ x, const float* __restrict__ y,
               const unsigned* __restrict__ pi, int N) {
    const int role = blockIdx.x & 1;
    const int b    = blockIdx.x >> 1;
    const int stride = HALFB * GNT;

    __shared__ float Ps[73];
    if (threadIdx.x < 73) Ps[threadIdx.x] = g_P[threadIdx.x];
    __syncthreads();

    float acc[73];
#pragma unroll
    for (int t = 0; t < 73; t++) acc[t] = 0.f;
    float S = 0.f;

    int i0 = b * GNT + threadIdx.x;
    unsigned rown = 0;
    if (i0 < N) rown = role ? __ldg(pi + i0) : (unsigned)i0;

    for (int i = i0; i < N; i += stride) {
        unsigned row = rown;
        int inx = i + stride;
        if (inx < N) rown = role ? __ldg(pi + inx) : (unsigned)inx;

        float inp[16];
        load8(x, (unsigned)i, inp);
        load8(y, row, inp + 8);

        float h[4];
        float s = Ps[72];
#pragma unroll
        for (int k = 0; k < 4; k++) {
            float ua = Ps[64 + k], ub = 0.f;
#pragma unroll
            for (int j = 0; j < 8; j++) {
                ua = fmaf(Ps[k * 16 + j],     inp[j],     ua);
                ub = fmaf(Ps[k * 16 + 8 + j], inp[8 + j], ub);
            }
            float hk = ftanh(ua + ub);
            h[k] = hk;
            s = fmaf(Ps[68 + k], hk, s);
        }
        float o = ftanh(s);
        float f = role ? 2.f * o : o;       // ALPHA=2: f2 = 2*est, f1 = est
        float w = __expf(f);                // no shift needed: |f| <= 2
        S += w;

        float d = w * (1.f - o * o);
        acc[72] += d;
#pragma unroll
        for (int k = 0; k < 4; k++) {
            acc[68 + k] = fmaf(d, h[k], acc[68 + k]);
            float e = d * Ps[68 + k] * (1.f - h[k] * h[k]);
            acc[64 + k] += e;
#pragma unroll
            for (int j = 0; j < 16; j++)
                acc[k * 16 + j] = fmaf(e, inp[j], acc[k * 16 + j]);
        }
    }

    // --- deterministic block reduction of 73 accumulators ---
#pragma unroll
    for (int t = 0; t < 73; t++) {
        float v = acc[t];
#pragma unroll
        for (int o = 16; o > 0; o >>= 1) v += __shfl_down_sync(0xffffffffu, v, o);
        acc[t] = v;
    }
    __shared__ float wsum[GNT / 32][73];
    int wid = threadIdx.x >> 5, lane = threadIdx.x & 31;
    if (lane == 0) {
#pragma unroll
        for (int t = 0; t < 73; t++) wsum[wid][t] = acc[t];
    }
    __syncthreads();
    if (threadIdx.x < 73) {
        float s = 0.f;
#pragma unroll
        for (int w = 0; w < GNT / 32; w++) s += wsum[w][threadIdx.x];
        g_partial[role][threadIdx.x][b] = s;
    }

    // --- deterministic block reduction of S (fp64 tree) ---
    __shared__ double red[GNT];
    red[threadIdx.x] = (double)S;
    __syncthreads();
    for (int o = GNT / 2; o > 0; o >>= 1) {
        if (threadIdx.x < (unsigned)o) red[threadIdx.x] += red[threadIdx.x + o];
        __syncthreads();
    }
    if (threadIdx.x == 0) g_S[role][b] = red[0];
}

// ============================================================================
// Parallel reduction: 148 blocks (rows 0..145 grads, 146/147 S sums)
// ============================================================================
__global__ void __launch_bounds__(256)
rmi_reduce(void) {
    int row = blockIdx.x, t = threadIdx.x;
    __shared__ double red[256];
    double s = 0.0;
    if (row < 146) {
        int role = row >= 73 ? 1 : 0;
        int p = role ? row - 73 : row;
        const float* src = &g_partial[role][p][0];
        for (int bb = t; bb < HALFB; bb += 256) s += (double)__ldg(src + bb);
    } else {
        int role = row - 146;
        for (int bb = t; bb < HALFB; bb += 256) s += g_S[role][bb];
    }
    red[t] = s;
    __syncthreads();
    for (int o = 128; o > 0; o >>= 1) {
        if (t < o) red[t] += red[t + o];
        __syncthreads();
    }
    if (t == 0) {
        if (row < 146) {
            int role = row >= 73 ? 1 : 0;
            int p = role ? row - 73 : row;
            g_G[role][p] = red[0];
        } else {
            g_Stot[row - 146] = red[0];
        }
    }
}

// ============================================================================
// Adam + loss (frozen)
// ============================================================================
__global__ void __launch_bounds__(128)
rmi_adam(int step, float bc1, float bc2, double logN) {
    double S1 = g_Stot[0], S2 = g_Stot[1];
    if (threadIdx.x == 0) {
        double t1 = log(S1) - logN;              // lse(f1) - logN
        double t2 = 0.5 * (log(S2) - logN);      // (lse(f2) - logN)/ALPHA
        g_losses[step] = (float)(t1 - t2);
    }
    if (threadIdx.x < 73) {
        int t = threadIdx.x;
        float g = (float)(g_G[1][t] / S2 - g_G[0][t] / S1);
        float m = 0.9f   * g_m[t] + 0.1f   * g;
        float v = 0.999f * g_v[t] + 0.001f * g * g;
        g_m[t] = m; g_v[t] = v;
        g_P[t] -= 1e-3f * (m / bc1) / (sqrtf(v / bc2) + 1e-8f);
    }
}

__global__ void rmi_write_out(float* __restrict__ out, int out_size) {
    for (int i = threadIdx.x; i < out_size; i += blockDim.x) {
        float v;
        if (out_size == NSTEPS)      v = g_losses[i];
        else if (out_size == 1)      v = g_losses[NSTEPS - 1];
        else {
            if (i == 0)              v = g_losses[NSTEPS - 1];
            else if (i <= NSTEPS)    v = g_losses[i - 1];
            else                     v = 0.f;
        }
        out[i] = v;
    }
}

// ============================================================================
// Host driver (graph-capturable: plain kernel launches only)
// ============================================================================
extern "C" void kernel_launch(void* const* d_in, const int* in_sizes, int n_in,
                              void* d_out, int out_size) {
    const float* x  = (const float*)d_in[0];
    const float* y  = (const float*)d_in[1];
    const float* w1 = (const float*)d_in[2];
    const float* b1 = (const float*)d_in[3];
    const float* w2 = (const float*)d_in[4];
    const float* b2 = (const float*)d_in[5];
    int N = in_sizes[0] / 8;
    if (N > MAXN) N = MAXN;

    // --- shuffle subkeys (host, input-independent, deterministic) ---
    SubKeys subk[2];
    for (int s = 0; s < NSEG; s++) {
        unsigned K0, K1;
        tf2x32(0u, 42u, 0u, (unsigned)s, K0, K1);
        for (int r = 0; r < 2; r++) {
            unsigned nk0, nk1, sb0, sb1;
            tf2x32(K0, K1, 0u, 0u, nk0, nk1);
            tf2x32(K0, K1, 0u, 1u, sb0, sb1);
            subk[r].k0[s] = sb0; subk[r].k1[s] = sb1;
            K0 = nk0; K1 = nk1;
        }
    }

    unsigned *v1p, *pp;
    cudaGetSymbolAddress((void**)&v1p, g_v1);
    cudaGetSymbolAddress((void**)&pp, g_perms);

    // --- launches: slot 3 = scatter0 (or slot 5 = bsort0 control) ---
    const int cps = (N + CHUNK - 1) / CHUNK;
    rmi_init_params<<<1, 128>>>(w1, b1, w2, b2);                // 0
    rmi_zero_cursors<<<64, 512>>>(0);                           // 1
    rmi_zero_cursors<<<64, 512>>>(1);                           // 2
    rmi_scatter<<<NSEG * cps, SCAT_T>>>(subk[0], N, cps, 0);    // 3  <- probe A
    rmi_scan<<<NSEG, 1024>>>(N, 0);                             // 4
    rmi_bucket_sort<0><<<NSEG << BBITS, SORT_T>>>(N, v1p);      // 5  <- probe B (control)
    rmi_scatter<<<NSEG * cps, SCAT_T>>>(subk[1], N, cps, 1);    // 6
    rmi_scan<<<NSEG, 1024>>>(N, 1);                             // 7
    rmi_bucket_sort<1><<<NSEG << BBITS, SORT_T>>>(N, pp);       // 8

    // --- 8 fused training steps ---
    const double logN = log((double)N);
    for (int s = 0; s < NSTEPS; s++) {
        const unsigned* pi = pp + (size_t)s * N;
        rmi_fused_step<<<2 * HALFB, GNT>>>(x, y, pi, N);
        rmi_reduce<<<148, 256>>>();
        double t = (double)(s + 1);
        float bc1 = (float)(1.0 - pow(0.9,   t));
        float bc2 = (float)(1.0 - pow(0.999, t));
        rmi_adam<<<1, 128>>>(s, bc1, bc2, logN);
    }

    rmi_write_out<<<1, 32>>>((float*)d_out, out_size);
}

// round 16
// speedup vs baseline: 1.6473x; 1.1557x over previous
#include <cuda_runtime.h>
#include <cstdint>
#include <math.h>

// ============================================================================
// Problem constants
// ============================================================================
#define MAXN    1048576
#define NSTEPS  8
#define NSEG    8               // 8 permutations (one per training step)
#define HALFB   296             // blocks per role; grid = 592 = 148 SMs x 4 CTAs (1 wave)
#define GNT     128             // threads per block in step kernel

// --- permutation sort configuration ---
#define BBITS   11              // MSD bucket bits
#define NBKT    (1 << BBITS)    // 2048 buckets per segment
#define LOWBITS (32 - BBITS)    // 21 low key bits
#define LOWMASK ((1u << LOWBITS) - 1u)
#define POSBITS 21              // position field (N <= 2^20)
#define POSMASK ((1u << POSBITS) - 1u)
#define CAPR    768             // fixed region capacity (avg 512, +11 sigma)
#define SORT_T  128
#define SORT_I  6               // 128*6 = 768 = CAPR
#define CAPF    (SORT_T * SORT_I)
#define SUBB    8               // in-bucket counting-sort bits (key bits [13,21))
#define NSUB    (1 << SUBB)     // 256 sub-buckets, avg 3 elements each
#define M34     ((1ull << 34) - 1ull)   // residue: (rem13 key << 21) | pos
#define M42     ((1ull << 42) - 1ull)   // payload: (low21 key << 21) | pos
#define SCAT_T  512
#define SCAT_I  16
#define CHUNK   (SCAT_T * SCAT_I)   // 8192 elements per scatter CTA
#define CPAD    8               // cursor padding (32B stride)
#define SMEM_SCAT (CHUNK * 8 + NBKT * 4 * 3)   // 90112 bytes

struct SubKeys { unsigned k0[NSEG]; unsigned k1[NSEG]; };

// ============================================================================
// Static device scratch (no dynamic allocation allowed)
// ============================================================================
__device__ __align__(256) unsigned long long g_pay[NSEG * NBKT * (size_t)CAPR]; // (low21key<<21)|pos
__device__ __align__(256) unsigned g_v1[NSEG * MAXN];    // round-1 result
__device__ __align__(256) unsigned g_perms[NSEG * MAXN]; // final permutations
__device__ unsigned g_cursor[2][NSEG * NBKT * CPAD];
__device__ unsigned g_base[2][NSEG * NBKT];

__device__ float  g_P[73];                    // [0..63]=w1, [64..67]=b1, [68..71]=w2, [72]=b2
__device__ float  g_m[73];
__device__ float  g_v[73];
__device__ float  g_partial[2][73][HALFB];
__device__ double g_S[2][HALFB];
__device__ double g_G[2][73];
__device__ double g_Stot[2];
__device__ float  g_losses[NSTEPS];

// ============================================================================
// Threefry2x32 — exact JAX implementation
// ============================================================================
__host__ __device__ __forceinline__ void tf2x32(unsigned k0, unsigned k1,
                                                unsigned c0, unsigned c1,
                                                unsigned &o0, unsigned &o1) {
    unsigned ks0 = k0, ks1 = k1, ks2 = k0 ^ k1 ^ 0x1BD11BDAu;
    unsigned x0 = c0 + ks0, x1 = c1 + ks1;
#define TFR(r) { x0 += x1; x1 = (x1 << (r)) | (x1 >> (32 - (r))); x1 ^= x0; }
    TFR(13) TFR(15) TFR(26) TFR(6)
    x0 += ks1; x1 += ks2 + 1u;
    TFR(17) TFR(29) TFR(16) TFR(24)
    x0 += ks2; x1 += ks0 + 2u;
    TFR(13) TFR(15) TFR(26) TFR(6)
    x0 += ks0; x1 += ks1 + 3u;
    TFR(17) TFR(29) TFR(16) TFR(24)
    x0 += ks1; x1 += ks2 + 4u;
    TFR(13) TFR(15) TFR(26) TFR(6)
    x0 += ks2; x1 += ks0 + 5u;
#undef TFR
    o0 = x0; o1 = x1;
}

__device__ __forceinline__ unsigned rnd_bits(const SubKeys& sk, int s, unsigned p) {
    unsigned a, b;
    tf2x32(sk.k0[s], sk.k1[s], 0u, p, a, b);
    return a ^ b;   // partitionable-threefry 32-bit random_bits
}

// ============================================================================
// Init kernels
// ============================================================================
__global__ void rmi_init_params(const float* __restrict__ w1,
                                const float* __restrict__ b1,
                                const float* __restrict__ w2,
                                const float* __restrict__ b2) {
    int t = threadIdx.x;
    if (t < 64)       g_P[t] = w1[t];
    else if (t < 68)  g_P[t] = b1[t - 64];
    else if (t < 72)  g_P[t] = w2[t - 68];
    else if (t == 72) g_P[72] = b2[0];
    if (t < 73) { g_m[t] = 0.f; g_v[t] = 0.f; }
}

__global__ void rmi_zero_cursors(int round) {
    int gid = blockIdx.x * blockDim.x + threadIdx.x;
    int tot = NSEG * NBKT * CPAD;
    for (int i = gid; i < tot; i += gridDim.x * blockDim.x)
        g_cursor[round][i] = 0;
}

// ============================================================================
// Scatter v2: CTA counting sort -> bucket-ordered smem staging -> one global
// atomic per touched bucket (range reservation) -> run-coalesced copy-out.
// Staged word packs the bucket id in bits [42,53) so no separate array.
// Cuts global atomics ~4x and payload L2 sectors ~3x vs direct scatter.
// ============================================================================
extern __shared__ unsigned long long rmi_dyn[];

__global__ void __launch_bounds__(SCAT_T)
rmi_scatter(SubKeys sk, int N, int cps, int round) {
    unsigned long long* stage = rmi_dyn;                        // CHUNK x 8B
    unsigned* cnt  = (unsigned*)(stage + CHUNK);                // NBKT
    unsigned* loff = cnt + NBKT;                                // NBKT
    unsigned* lcur = loff + NBKT;                               // NBKT
    __shared__ unsigned wsc[SCAT_T / 32];

    const int s = blockIdx.x / cps, c = blockIdx.x % cps;
    const int tid = threadIdx.x;
    const int p0 = c * CHUNK;

    for (int b = tid; b < NBKT; b += SCAT_T) cnt[b] = 0;
    __syncthreads();

    // Phase 1: keys + per-bucket counts
    unsigned bits[SCAT_I];
#pragma unroll
    for (int j = 0; j < SCAT_I; j++) {
        int p = p0 + j * SCAT_T + tid;
        unsigned bb = 0u;
        if (p < N) {
            bb = rnd_bits(sk, s, (unsigned)p);
            atomicAdd(&cnt[bb >> LOWBITS], 1u);
        }
        bits[j] = bb;
    }
    __syncthreads();

    // Phase 2: CTA-wide exclusive scan of 2048 counts (4 per thread)
    {
        unsigned a[4], tsum = 0;
#pragma unroll
        for (int q = 0; q < 4; q++) { a[q] = cnt[tid * 4 + q]; tsum += a[q]; }
        int lane = tid & 31, w = tid >> 5;
        unsigned sv = tsum;
#pragma unroll
        for (int o = 1; o < 32; o <<= 1) {
            unsigned u = __shfl_up_sync(0xffffffffu, sv, o);
            if (lane >= o) sv += u;
        }
        if (lane == 31) wsc[w] = sv;
        __syncthreads();
        unsigned wo = 0;
#pragma unroll
        for (int q = 0; q < SCAT_T / 32; q++) if (q < w) wo += wsc[q];
        unsigned excl = wo + sv - tsum;
#pragma unroll
        for (int q = 0; q < 4; q++) {
            loff[tid * 4 + q] = excl;
            lcur[tid * 4 + q] = excl;
            excl += a[q];
        }
    }
    __syncthreads();

    // Phase 3: stage payloads bucket-ordered; pack bucket id in bits [42,53)
#pragma unroll
    for (int j = 0; j < SCAT_I; j++) {
        int p = p0 + j * SCAT_T + tid;
        if (p < N) {
            unsigned bb = bits[j];
            unsigned b  = bb >> LOWBITS;
            unsigned slot = atomicAdd(&lcur[b], 1u);
            stage[slot] = ((unsigned long long)b << 42)
                        | ((unsigned long long)(bb & LOWMASK) << POSBITS)
                        | (unsigned long long)(unsigned)p;
        }
    }
    __syncthreads();

    // Phase 4: reserve global ranges (one atomic per touched bucket);
    // reuse loff[b] as delta = gbase - local_offset
    unsigned* cursor = &g_cursor[round][s * NBKT * CPAD];
    for (int b = tid; b < NBKT; b += SCAT_T) {
        unsigned cc = cnt[b];
        if (cc) {
            unsigned gb = atomicAdd(&cursor[b * CPAD], cc);
            loff[b] = gb - loff[b];
        }
    }
    __syncthreads();

    // Phase 5: copy out; consecutive slots share buckets in runs (~4) so
    // warps write mostly-contiguous addresses
    int total = N - p0; if (total > CHUNK) total = CHUNK;
    for (int i = tid; i < total; i += SCAT_T) {
        unsigned long long v = stage[i];
        unsigned b = (unsigned)(v >> 42);
        unsigned gslot = loff[b] + (unsigned)i;       // delta + slot index
        if (gslot < CAPR)                             // overflow P ~ 1e-20
            g_pay[(size_t)(s * NBKT + b) * CAPR + gslot] = v & M42;
    }
}

// One block per segment: exclusive scan of 2048 bucket counts -> absolute bases.
__global__ void __launch_bounds__(1024)
rmi_scan(int N, int round) {
    int s = blockIdx.x, t = threadIdx.x;
    const unsigned* cur = &g_cursor[round][s * NBKT * CPAD];
    unsigned c0 = cur[(2 * t) * CPAD],     n0 = c0 > CAPR ? CAPR : c0;
    unsigned c1 = cur[(2 * t + 1) * CPAD], n1 = c1 > CAPR ? CAPR : c1;
    unsigned tsum = n0 + n1;

    int lane = t & 31, w = t >> 5;
    unsigned v = tsum;
#pragma unroll
    for (int o = 1; o < 32; o <<= 1) {
        unsigned u = __shfl_up_sync(0xffffffffu, v, o);
        if (lane >= o) v += u;
    }
    __shared__ unsigned wsums[32];
    if (lane == 31) wsums[w] = v;
    __syncthreads();
    if (w == 0) {
        unsigned x = wsums[lane];
#pragma unroll
        for (int o = 1; o < 32; o <<= 1) {
            unsigned u = __shfl_up_sync(0xffffffffu, x, o);
            if (lane >= o) x += u;
        }
        wsums[lane] = x - wsums[lane];   // exclusive warp offsets
    }
    __syncthreads();
    unsigned excl = wsums[w] + (v - tsum) + (unsigned)(s * N);
    g_base[round][s * NBKT + 2 * t]     = excl;
    g_base[round][s * NBKT + 2 * t + 1] = excl + n0;
}

// ============================================================================
// In-bucket sort (frozen from R14/R15 passer)
// ============================================================================
template <int ROUND>
__global__ void __launch_bounds__(SORT_T)
rmi_bucket_sort(int N, unsigned* __restrict__ out) {
    int s = blockIdx.x >> BBITS, b = blockIdx.x & (NBKT - 1);
    int sb = s * NBKT + b;
    unsigned n = g_cursor[ROUND][sb * CPAD];
    if (n > CAPR) n = CAPR;
    unsigned base = g_base[ROUND][sb];

    __shared__ unsigned long long buf[CAPF];   // 6 KB
    __shared__ unsigned cnt[NSUB];
    __shared__ unsigned off[NSUB];
    __shared__ unsigned cur[NSUB];
    __shared__ unsigned ws4[4];

    const int tid = threadIdx.x;
    for (int i = tid; i < NSUB; i += SORT_T) cnt[i] = 0;
    __syncthreads();

    const unsigned long long* pay = &g_pay[(size_t)sb * CAPR];
    unsigned long long v[SORT_I];
#pragma unroll
    for (int k = 0; k < SORT_I; k++) {
        unsigned r = (unsigned)(k * SORT_T + tid);
        if (r < n) {
            v[k] = pay[r];
            atomicAdd(&cnt[(unsigned)(v[k] >> 34)], 1u);
        } else v[k] = ~0ull;
    }
    __syncthreads();

    {
        unsigned a0 = cnt[2 * tid], a1 = cnt[2 * tid + 1];
        unsigned tsum = a0 + a1;
        int lane = tid & 31, w = tid >> 5;
        unsigned sv = tsum;
#pragma unroll
        for (int o = 1; o < 32; o <<= 1) {
            unsigned u = __shfl_up_sync(0xffffffffu, sv, o);
            if (lane >= o) sv += u;
        }
        if (lane == 31) ws4[w] = sv;
        __syncthreads();
        unsigned wo = 0;
        for (int w2 = 0; w2 < 4; w2++) if (w2 < w) wo += ws4[w2];
        unsigned excl = wo + sv - tsum;
        off[2 * tid] = excl;          cur[2 * tid] = excl;
        off[2 * tid + 1] = excl + a0; cur[2 * tid + 1] = excl + a0;
    }
    __syncthreads();

#pragma unroll
    for (int k = 0; k < SORT_I; k++) {
        unsigned r = (unsigned)(k * SORT_T + tid);
        if (r < n) {
            unsigned sub = (unsigned)(v[k] >> 34);
            unsigned slot = atomicAdd(&cur[sub], 1u);
            buf[slot] = v[k] & M34;
        }
    }
    __syncthreads();

    for (int sub = tid; sub < NSUB; sub += SORT_T) {
        unsigned b0 = off[sub], L = cnt[sub];
        for (unsigned i = 1; i < L; i++) {
            unsigned long long key = buf[b0 + i];
            int j = (int)i - 1;
            while (j >= 0 && buf[b0 + j] > key) {
                buf[b0 + j + 1] = buf[b0 + j];
                j--;
            }
            buf[b0 + j + 1] = key;
        }
    }
    __syncthreads();

    for (unsigned r = tid; r < n; r += SORT_T) {
        unsigned pos = (unsigned)buf[r] & POSMASK;
        unsigned val = (ROUND == 0) ? pos : __ldg(&g_v1[s * N + pos]);
        out[base + r] = val;
    }
}

// ============================================================================
// Tiny-MLP helpers
// ============================================================================
__device__ __forceinline__ void load8(const float* __restrict__ base, unsigned row,
                                      float* __restrict__ dst) {
    const float4* p = (const float4*)base + 2ull * row;
    float4 a = __ldg(p), b = __ldg(p + 1);
    dst[0] = a.x; dst[1] = a.y; dst[2] = a.z; dst[3] = a.w;
    dst[4] = b.x; dst[5] = b.y; dst[6] = b.z; dst[7] = b.w;
}

__device__ __forceinline__ float ftanh(float x) {
    float r;
    asm("tanh.approx.f32 %0, %1;" : "=f"(r) : "f"(x));
    return r;
}

// ============================================================================
// Fused per-step pass (frozen from R15 passer)
// ============================================================================
__global__ void __launch_bounds__(GNT)
rmi_fused_step(const float* __restrict__ x, const float* __restrict__ y,
               const unsigned* __restrict__ pi, int N) {
    const int role = blockIdx.x & 1;
    const int b    = blockIdx.x >> 1;
    const int stride = HALFB * GNT;

    __shared__ float Ps[73];
    if (threadIdx.x < 73) Ps[threadIdx.x] = g_P[threadIdx.x];
    __syncthreads();

    float acc[73];
#pragma unroll
    for (int t = 0; t < 73; t++) acc[t] = 0.f;
    float S = 0.f;

    int i0 = b * GNT + threadIdx.x;
    unsigned rown = 0;
    if (i0 < N) rown = role ? __ldg(pi + i0) : (unsigned)i0;

    for (int i = i0; i < N; i += stride) {
        unsigned row = rown;
        int inx = i + stride;
        if (inx < N) rown = role ? __ldg(pi + inx) : (unsigned)inx;

        float inp[16];
        load8(x, (unsigned)i, inp);
        load8(y, row, inp + 8);

        float h[4];
        float s = Ps[72];
#pragma unroll
        for (int k = 0; k < 4; k++) {
            float ua = Ps[64 + k], ub = 0.f;
#pragma unroll
            for (int j = 0; j < 8; j++) {
                ua = fmaf(Ps[k * 16 + j],     inp[j],     ua);
                ub = fmaf(Ps[k * 16 + 8 + j], inp[8 + j], ub);
            }
            float hk = ftanh(ua + ub);
            h[k] = hk;
            s = fmaf(Ps[68 + k], hk, s);
        }
        float o = ftanh(s);
        float f = role ? 2.f * o : o;       // ALPHA=2: f2 = 2*est, f1 = est
        float w = __expf(f);                // no shift needed: |f| <= 2
        S += w;

        float d = w * (1.f - o * o);
        acc[72] += d;
#pragma unroll
        for (int k = 0; k < 4; k++) {
            acc[68 + k] = fmaf(d, h[k], acc[68 + k]);
            float e = d * Ps[68 + k] * (1.f - h[k] * h[k]);
            acc[64 + k] += e;
#pragma unroll
            for (int j = 0; j < 16; j++)
                acc[k * 16 + j] = fmaf(e, inp[j], acc[k * 16 + j]);
        }
    }

    // --- deterministic block reduction of 73 accumulators ---
#pragma unroll
    for (int t = 0; t < 73; t++) {
        float v = acc[t];
#pragma unroll
        for (int o = 16; o > 0; o >>= 1) v += __shfl_down_sync(0xffffffffu, v, o);
        acc[t] = v;
    }
    __shared__ float wsum[GNT / 32][73];
    int wid = threadIdx.x >> 5, lane = threadIdx.x & 31;
    if (lane == 0) {
#pragma unroll
        for (int t = 0; t < 73; t++) wsum[wid][t] = acc[t];
    }
    __syncthreads();
    if (threadIdx.x < 73) {
        float s = 0.f;
#pragma unroll
        for (int w = 0; w < GNT / 32; w++) s += wsum[w][threadIdx.x];
        g_partial[role][threadIdx.x][b] = s;
    }

    // --- deterministic block reduction of S (fp64 tree) ---
    __shared__ double red[GNT];
    red[threadIdx.x] = (double)S;
    __syncthreads();
    for (int o = GNT / 2; o > 0; o >>= 1) {
        if (threadIdx.x < (unsigned)o) red[threadIdx.x] += red[threadIdx.x + o];
        __syncthreads();
    }
    if (threadIdx.x == 0) g_S[role][b] = red[0];
}

// ============================================================================
// Parallel reduction: 148 blocks (rows 0..145 grads, 146/147 S sums)
// ============================================================================
__global__ void __launch_bounds__(256)
rmi_reduce(void) {
    int row = blockIdx.x, t = threadIdx.x;
    __shared__ double red[256];
    double s = 0.0;
    if (row < 146) {
        int role = row >= 73 ? 1 : 0;
        int p = role ? row - 73 : row;
        const float* src = &g_partial[role][p][0];
        for (int bb = t; bb < HALFB; bb += 256) s += (double)__ldg(src + bb);
    } else {
        int role = row - 146;
        for (int bb = t; bb < HALFB; bb += 256) s += g_S[role][bb];
    }
    red[t] = s;
    __syncthreads();
    for (int o = 128; o > 0; o >>= 1) {
        if (t < o) red[t] += red[t + o];
        __syncthreads();
    }
    if (t == 0) {
        if (row < 146) {
            int role = row >= 73 ? 1 : 0;
            int p = role ? row - 73 : row;
            g_G[role][p] = red[0];
        } else {
            g_Stot[row - 146] = red[0];
        }
    }
}

// ============================================================================
// Adam + loss (frozen)
// ============================================================================
__global__ void __launch_bounds__(128)
rmi_adam(int step, float bc1, float bc2, double logN) {
    double S1 = g_Stot[0], S2 = g_Stot[1];
    if (threadIdx.x == 0) {
        double t1 = log(S1) - logN;              // lse(f1) - logN
        double t2 = 0.5 * (log(S2) - logN);      // (lse(f2) - logN)/ALPHA
        g_losses[step] = (float)(t1 - t2);
    }
    if (threadIdx.x < 73) {
        int t = threadIdx.x;
        float g = (float)(g_G[1][t] / S2 - g_G[0][t] / S1);
        float m = 0.9f   * g_m[t] + 0.1f   * g;
        float v = 0.999f * g_v[t] + 0.001f * g * g;
        g_m[t] = m; g_v[t] = v;
        g_P[t] -= 1e-3f * (m / bc1) / (sqrtf(v / bc2) + 1e-8f);
    }
}

__global__ void rmi_write_out(float* __restrict__ out, int out_size) {
    for (int i = threadIdx.x; i < out_size; i += blockDim.x) {
        float v;
        if (out_size == NSTEPS)      v = g_losses[i];
        else if (out_size == 1)      v = g_losses[NSTEPS - 1];
        else {
            if (i == 0)              v = g_losses[NSTEPS - 1];
            else if (i <= NSTEPS)    v = g_losses[i - 1];
            else                     v = 0.f;
        }
        out[i] = v;
    }
}

// ============================================================================
// Host driver (graph-capturable: plain kernel launches only)
// ============================================================================
extern "C" void kernel_launch(void* const* d_in, const int* in_sizes, int n_in,
                              void* d_out, int out_size) {
    const float* x  = (const float*)d_in[0];
    const float* y  = (const float*)d_in[1];
    const float* w1 = (const float*)d_in[2];
    const float* b1 = (const float*)d_in[3];
    const float* w2 = (const float*)d_in[4];
    const float* b2 = (const float*)d_in[5];
    int N = in_sizes[0] / 8;
    if (N > MAXN) N = MAXN;

    // scatter uses 88 KB dynamic smem (idempotent attribute set; not a stream op)
    cudaFuncSetAttribute(rmi_scatter,
                         cudaFuncAttributeMaxDynamicSharedMemorySize, SMEM_SCAT);

    // --- shuffle subkeys (host, input-independent, deterministic) ---
    SubKeys subk[2];
    for (int s = 0; s < NSEG; s++) {
        unsigned K0, K1;
        tf2x32(0u, 42u, 0u, (unsigned)s, K0, K1);
        for (int r = 0; r < 2; r++) {
            unsigned nk0, nk1, sb0, sb1;
            tf2x32(K0, K1, 0u, 0u, nk0, nk1);
            tf2x32(K0, K1, 0u, 1u, sb0, sb1);
            subk[r].k0[s] = sb0; subk[r].k1[s] = sb1;
            K0 = nk0; K1 = nk1;
        }
    }

    unsigned *v1p, *pp;
    cudaGetSymbolAddress((void**)&v1p, g_v1);
    cudaGetSymbolAddress((void**)&pp, g_perms);

    // --- launches: slot 3 = scatter0 (probe) ---
    const int cps = (N + CHUNK - 1) / CHUNK;
    rmi_init_params<<<1, 128>>>(w1, b1, w2, b2);                        // 0
    rmi_zero_cursors<<<64, 512>>>(0);                                   // 1
    rmi_zero_cursors<<<64, 512>>>(1);                                   // 2
    rmi_scatter<<<NSEG * cps, SCAT_T, SMEM_SCAT>>>(subk[0], N, cps, 0); // 3  <- probe
    rmi_scan<<<NSEG, 1024>>>(N, 0);                                     // 4
    rmi_bucket_sort<0><<<NSEG << BBITS, SORT_T>>>(N, v1p);              // 5
    rmi_scatter<<<NSEG * cps, SCAT_T, SMEM_SCAT>>>(subk[1], N, cps, 1); // 6
    rmi_scan<<<NSEG, 1024>>>(N, 1);                                     // 7
    rmi_bucket_sort<1><<<NSEG << BBITS, SORT_T>>>(N, pp);               // 8

    // --- 8 fused training steps ---
    const double logN = log((double)N);
    for (int s = 0; s < NSTEPS; s++) {
        const unsigned* pi = pp + (size_t)s * N;
        rmi_fused_step<<<2 * HALFB, GNT>>>(x, y, pi, N);
        rmi_reduce<<<148, 256>>>();
        double t = (double)(s + 1);
        float bc1 = (float)(1.0 - pow(0.9,   t));
        float bc2 = (float)(1.0 - pow(0.999, t));
        rmi_adam<<<1, 128>>>(s, bc1, bc2, logN);
    }

    rmi_write_out<<<1, 32>>>((float*)d_out, out_size);
}